// round 2
// baseline (speedup 1.0000x reference)
#include <cuda_runtime.h>

#define B_   512
#define H_   512
#define L_   512
#define I_   32
#define DT_  0.042f

#define BM   32
#define BN   64
#define BK   16
#define AP   36          // padded BM (multiple of 4 for float4-aligned rows)
#define GRID_ 128
#define NTHR 256
#define KCH  (H_ / BK)   // 32 k-chunks

// Persistent device state (3 MB total, L2-resident)
__device__ float g_hy[B_ * H_];
__device__ float g_hz[B_ * H_];
__device__ float g_T [B_ * H_];
__device__ unsigned g_bar_count = 0u;
__device__ volatile unsigned g_bar_gen = 0u;

__device__ __forceinline__ void grid_barrier(unsigned gen) {
    __syncthreads();
    if (threadIdx.x == 0) {
        __threadfence();
        if (atomicAdd(&g_bar_count, 1u) == (unsigned)(GRID_ - 1)) {
            g_bar_count = 0u;
            __threadfence();
            g_bar_gen = gen + 1u;      // release
        } else {
            while (g_bar_gen == gen) { }  // volatile spin
            __threadfence();              // acquire
        }
    }
    __syncthreads();
}

// C_tile(32x64) [SGN>0: +=, SGN<0: -=]  A[i0..i0+31, 0..511] * B[0..511, j0..j0+63]
// A, B row-major with leading dim 512. Double-buffered SMEM, reg-staged loads.
template<int SGN>
__device__ __forceinline__ void gemm_tile(
    const float* __restrict__ A, const float* __restrict__ Bm,
    int i0, int j0, int tid, int tx, int ty,
    float As[2][BK][AP], float Bs[2][BK][BN],
    float acc[4][2])
{
    float ra[2], rb[4];

    // prologue: chunk 0
    #pragma unroll
    for (int e = 0; e < 2; ++e) {
        int idx = tid + e * NTHR; int r = idx >> 4, c = idx & 15;
        ra[e] = A[(i0 + r) * H_ + c];
    }
    #pragma unroll
    for (int e = 0; e < 4; ++e) {
        int idx = tid + e * NTHR; int c = idx >> 6, jj = idx & 63;
        rb[e] = Bm[c * H_ + j0 + jj];
    }
    #pragma unroll
    for (int e = 0; e < 2; ++e) {
        int idx = tid + e * NTHR; int r = idx >> 4, c = idx & 15;
        As[0][c][r] = ra[e];
    }
    #pragma unroll
    for (int e = 0; e < 4; ++e) {
        int idx = tid + e * NTHR; int c = idx >> 6, jj = idx & 63;
        Bs[0][c][jj] = rb[e];
    }
    __syncthreads();

    for (int kc = 0; kc < KCH; ++kc) {
        const int cur = kc & 1;
        const int k0n = (kc + 1) * BK;
        if (kc + 1 < KCH) {
            #pragma unroll
            for (int e = 0; e < 2; ++e) {
                int idx = tid + e * NTHR; int r = idx >> 4, c = idx & 15;
                ra[e] = A[(i0 + r) * H_ + k0n + c];
            }
            #pragma unroll
            for (int e = 0; e < 4; ++e) {
                int idx = tid + e * NTHR; int c = idx >> 6, jj = idx & 63;
                rb[e] = Bm[(k0n + c) * H_ + j0 + jj];
            }
        }
        #pragma unroll
        for (int kk = 0; kk < BK; ++kk) {
            float4 a = *reinterpret_cast<const float4*>(&As[cur][kk][ty * 4]);
            float2 b = *reinterpret_cast<const float2*>(&Bs[cur][kk][tx * 2]);
            if (SGN > 0) {
                acc[0][0] += a.x * b.x; acc[0][1] += a.x * b.y;
                acc[1][0] += a.y * b.x; acc[1][1] += a.y * b.y;
                acc[2][0] += a.z * b.x; acc[2][1] += a.z * b.y;
                acc[3][0] += a.w * b.x; acc[3][1] += a.w * b.y;
            } else {
                acc[0][0] -= a.x * b.x; acc[0][1] -= a.x * b.y;
                acc[1][0] -= a.y * b.x; acc[1][1] -= a.y * b.y;
                acc[2][0] -= a.z * b.x; acc[2][1] -= a.z * b.y;
                acc[3][0] -= a.w * b.x; acc[3][1] -= a.w * b.y;
            }
        }
        if (kc + 1 < KCH) {
            const int nb = cur ^ 1;
            #pragma unroll
            for (int e = 0; e < 2; ++e) {
                int idx = tid + e * NTHR; int r = idx >> 4, c = idx & 15;
                As[nb][c][r] = ra[e];
            }
            #pragma unroll
            for (int e = 0; e < 4; ++e) {
                int idx = tid + e * NTHR; int c = idx >> 6, jj = idx & 63;
                Bs[nb][c][jj] = rb[e];
            }
        }
        __syncthreads();
    }
}

__global__ void __launch_bounds__(NTHR, 1) coesn_kernel(
    const float* __restrict__ x,    const float* __restrict__ x2h,
    const float* __restrict__ h2h,  const float* __restrict__ h2hT,
    const float* __restrict__ bias, const float* __restrict__ gamma,
    const float* __restrict__ eps,  float* __restrict__ out, int write_final)
{
    __shared__ __align__(16) float As[2][BK][AP];
    __shared__ __align__(16) float Bs[2][BK][BN];
    __shared__ __align__(16) float Xs[I_][AP];
    __shared__ __align__(16) float X2s[I_][BN];

    const int tid = threadIdx.x;
    const int tx = tid & 31, ty = tid >> 5;
    const int bid = blockIdx.x;
    const int i0 = (bid >> 3) * BM;   // 16 row tiles
    const int j0 = (bid & 7) * BN;    // 8 col tiles

    unsigned gen = g_bar_gen;         // barrier generation persists across graph replays

    // persistent per-CTA data: x2h column slice, per-thread scalars
    #pragma unroll
    for (int e = 0; e < 8; ++e) {
        int idx = tid + e * NTHR; int p = idx >> 6, jj = idx & 63;
        X2s[p][jj] = x2h[p * H_ + j0 + jj];
    }
    const int jc = j0 + tx * 2;
    float bias_r[2] = { bias[jc],  bias[jc + 1]  };
    float gam_r[2]  = { gamma[jc], gamma[jc + 1] };
    float eps_r[2]  = { eps[jc],   eps[jc + 1]   };

    // zero state tile (re-run every launch/replay)
    #pragma unroll
    for (int e = 0; e < 8; ++e) {
        int idx = tid + e * NTHR; int r = idx >> 6, cc = idx & 63;
        g_hy[(i0 + r) * H_ + j0 + cc] = 0.f;
        g_hz[(i0 + r) * H_ + j0 + cc] = 0.f;
    }
    grid_barrier(gen); gen++;

    for (int t = 0; t < L_; ++t) {
        // ---- Phase 1: T = tanh(hy @ h2h + bias) ----
        float acc[4][2] = {{0.f,0.f},{0.f,0.f},{0.f,0.f},{0.f,0.f}};
        gemm_tile<1>(g_hy, h2h, i0, j0, tid, tx, ty, As, Bs, acc);
        #pragma unroll
        for (int m = 0; m < 4; ++m) {
            int row = i0 + ty * 4 + m;
            #pragma unroll
            for (int n = 0; n < 2; ++n)
                g_T[row * H_ + jc + n] = tanhf(acc[m][n] + bias_r[n]);
        }
        grid_barrier(gen); gen++;

        // ---- Phase 2: hz/hy update ----
        // x_t tile -> SMEM (transposed)
        #pragma unroll
        for (int e = 0; e < 4; ++e) {
            int idx = tid + e * NTHR; int r = idx >> 5, p = idx & 31;
            Xs[p][r] = x[(i0 + r) * (L_ * I_) + t * I_ + p];
        }
        __syncthreads();

        float ac2[4][2] = {{0.f,0.f},{0.f,0.f},{0.f,0.f},{0.f,0.f}};
        // + x_t @ x2h  (K = 32)
        #pragma unroll
        for (int p = 0; p < I_; ++p) {
            float4 a = *reinterpret_cast<const float4*>(&Xs[p][ty * 4]);
            float2 b = *reinterpret_cast<const float2*>(&X2s[p][tx * 2]);
            ac2[0][0] += a.x * b.x; ac2[0][1] += a.x * b.y;
            ac2[1][0] += a.y * b.x; ac2[1][1] += a.y * b.y;
            ac2[2][0] += a.z * b.x; ac2[2][1] += a.z * b.y;
            ac2[3][0] += a.w * b.x; ac2[3][1] += a.w * b.y;
        }
        // - h2h_T @ T  (K = 512)
        gemm_tile<-1>(h2hT, g_T, i0, j0, tid, tx, ty, As, Bs, ac2);

        // epilogue: integrate, write all_states
        #pragma unroll
        for (int m = 0; m < 4; ++m) {
            int row = i0 + ty * 4 + m;
            int obase = (row * L_ + t) * H_ + jc;
            #pragma unroll
            for (int n = 0; n < 2; ++n) {
                int idx = row * H_ + jc + n;
                float hyv = g_hy[idx], hzv = g_hz[idx];
                float hzn = hzv + DT_ * (ac2[m][n] - gam_r[n] * hyv - eps_r[n] * hzv);
                float hyn = hyv + DT_ * hzn;
                g_hz[idx] = hzn;
                g_hy[idx] = hyn;
                out[obase + n] = hyn;
            }
        }
        grid_barrier(gen); gen++;
    }

    // final hy (second output), if the harness expects it
    if (write_final) {
        #pragma unroll
        for (int e = 0; e < 8; ++e) {
            int idx = tid + e * NTHR; int r = idx >> 6, cc = idx & 63;
            int gi = (i0 + r) * H_ + j0 + cc;
            out[B_ * L_ * H_ + gi] = g_hy[gi];
        }
    }
}

extern "C" void kernel_launch(void* const* d_in, const int* in_sizes, int n_in,
                              void* d_out, int out_size) {
    const float* x    = (const float*)d_in[0];
    const float* x2h  = (const float*)d_in[1];
    const float* h2h  = (const float*)d_in[2];
    const float* h2hT = (const float*)d_in[3];
    const float* bias = (const float*)d_in[4];
    const float* gam  = (const float*)d_in[5];
    const float* eps  = (const float*)d_in[6];
    (void)in_sizes; (void)n_in;

    const int write_final = (out_size >= B_ * L_ * H_ + B_ * H_) ? 1 : 0;
    coesn_kernel<<<GRID_, NTHR>>>(x, x2h, h2h, h2hT, bias, gam, eps,
                                  (float*)d_out, write_final);
}

// round 5
// speedup vs baseline: 1.8395x; 1.8395x over previous
#include <cuda_runtime.h>
#include <cuda_fp16.h>
#include <cstdint>

#define Bq 512
#define Hq 512
#define Lq 512
#define Iq 32
#define DTF 0.042f
#define NCTA 64
#define NTHR 256

// ---- SMEM byte offsets ----
// A bufs: 2 buf x 2 part x (128 rows x 144B) = 73728
// B bufs: 2 buf x 2 part x (32  rows x 144B) = 18432
// X:      2 part x (128 x 80B)               = 20480
// BX:     2 part x (32  x 80B)               = 5120
// SC:     3 x 32 floats                      = 384
#define OFF_A   0
#define OFF_B   73728
#define OFF_X   92160
#define OFF_BX  112640
#define OFF_SC  117760
#define SMEM_TOT 118144

#define A_PART  18432u
#define A_BUF   36864u
#define B_PART  4608u
#define B_BUF   9216u
#define X_PART  10240u
#define BX_PART 2560u

// ---- persistent device state ----
__device__ __align__(256) __half g_hy_hi[Bq*Hq], g_hy_lo[Bq*Hq];
__device__ __align__(256) __half g_Tt_hi[Hq*Bq], g_Tt_lo[Hq*Bq];   // T^T: [h][b]
__device__ __align__(256) __half g_W1_hi[Hq*Hq], g_W1_lo[Hq*Hq];   // h2h^T: [h][k]
__device__ __align__(256) __half g_W2_hi[Hq*Hq], g_W2_lo[Hq*Hq];   // -h2hT: [b][j]
__device__ unsigned g_bar_count = 0u;
__device__ volatile unsigned g_bar_gen = 0u;

__device__ __forceinline__ uint32_t smem_u32(const void* p) {
    uint32_t a;
    asm("{ .reg .u64 t; cvta.to.shared.u64 t, %1; cvt.u32.u64 %0, t; }" : "=r"(a) : "l"(p));
    return a;
}
#define CP_ASYNC16(dst, src) \
    asm volatile("cp.async.cg.shared.global [%0], [%1], 16;" :: "r"(dst), "l"(src) : "memory")
#define CP_COMMIT() asm volatile("cp.async.commit_group;" ::: "memory")
#define CP_WAIT0()  asm volatile("cp.async.wait_group 0;" ::: "memory")
#define CP_WAIT1()  asm volatile("cp.async.wait_group 1;" ::: "memory")
#define LDSM4(r0,r1,r2,r3, addr) \
    asm volatile("ldmatrix.sync.aligned.m8n8.x4.shared.b16 {%0,%1,%2,%3}, [%4];" \
        : "=r"(r0), "=r"(r1), "=r"(r2), "=r"(r3) : "r"(addr))

__device__ __forceinline__ void mma16816(float* c, uint32_t a0, uint32_t a1, uint32_t a2,
                                         uint32_t a3, uint32_t b0, uint32_t b1) {
    asm volatile(
        "mma.sync.aligned.m16n8k16.row.col.f32.f16.f16.f32 "
        "{%0,%1,%2,%3}, {%4,%5,%6,%7}, {%8,%9}, {%0,%1,%2,%3};"
        : "+f"(c[0]), "+f"(c[1]), "+f"(c[2]), "+f"(c[3])
        : "r"(a0), "r"(a1), "r"(a2), "r"(a3), "r"(b0), "r"(b1));
}

// ---- staging (row-major padded SMEM rows of 144B; 64 k halves = 128B data) ----
__device__ __forceinline__ void stageA(uint32_t dst0, const __half* __restrict__ ghi,
                                       const __half* __restrict__ glo,
                                       int row0, int k0, int tid) {
    #pragma unroll
    for (int e = 0; e < 8; ++e) {                 // 2 part x 128 rows x 8 segs
        int idx = tid + e * NTHR;
        const __half* g = (e < 4) ? ghi : glo;
        uint32_t po = (e < 4) ? 0u : A_PART;
        int rem = idx & 1023, r = rem >> 3, seg = rem & 7;
        CP_ASYNC16(dst0 + po + (uint32_t)(r * 144 + seg * 16),
                   g + (size_t)(row0 + r) * 512 + k0 + seg * 8);
    }
}
__device__ __forceinline__ void stageB(uint32_t dst0, const __half* __restrict__ ghi,
                                       const __half* __restrict__ glo,
                                       int row0, int k0, int tid) {
    #pragma unroll
    for (int e = 0; e < 2; ++e) {                 // 2 part x 32 rows x 8 segs
        int idx = tid + e * NTHR;
        const __half* g = (e < 1) ? ghi : glo;
        uint32_t po = (e < 1) ? 0u : B_PART;
        int rem = idx & 255, r = rem >> 3, seg = rem & 7;
        CP_ASYNC16(dst0 + po + (uint32_t)(r * 144 + seg * 16),
                   g + (size_t)(row0 + r) * 512 + k0 + seg * 8);
    }
}

// one BK chunk: NKS k16-steps, 2 n16-blocks (N=32), split-fp16 (3 mma/k-step/n16)
template<int NKS>
__device__ __forceinline__ void compute_chunk(
    uint32_t aBase, uint32_t aPart, uint32_t aStr,
    uint32_t bBase, uint32_t bPart, uint32_t bStr,
    int w, int lane, float acc[4][4])
{
    const int m = lane >> 3, rr = lane & 7;
    const uint32_t aAddr = aBase + (uint32_t)(w * 16 + (m & 1) * 8 + rr) * aStr
                         + (uint32_t)((m >> 1) * 16);
    const uint32_t bAddr = bBase + (uint32_t)((m >> 1) * 8 + rr) * bStr
                         + (uint32_t)((m & 1) * 16);
    #pragma unroll
    for (int ks = 0; ks < NKS; ++ks) {
        uint32_t ah0, ah1, ah2, ah3, al0, al1, al2, al3;
        LDSM4(ah0, ah1, ah2, ah3, aAddr + ks * 32);
        LDSM4(al0, al1, al2, al3, aAddr + aPart + ks * 32);
        #pragma unroll
        for (int p = 0; p < 2; ++p) {
            uint32_t bh0, bh1, bh2, bh3, bl0, bl1, bl2, bl3;
            uint32_t ba = bAddr + (uint32_t)(p * 16) * bStr + ks * 32;
            LDSM4(bh0, bh1, bh2, bh3, ba);
            LDSM4(bl0, bl1, bl2, bl3, ba + bPart);
            mma16816(acc[2*p],   ah0, ah1, ah2, ah3, bh0, bh1);
            mma16816(acc[2*p],   ah0, ah1, ah2, ah3, bl0, bl1);
            mma16816(acc[2*p],   al0, al1, al2, al3, bh0, bh1);
            mma16816(acc[2*p+1], ah0, ah1, ah2, ah3, bh2, bh3);
            mma16816(acc[2*p+1], ah0, ah1, ah2, ah3, bl2, bl3);
            mma16816(acc[2*p+1], al0, al1, al2, al3, bh2, bh3);
        }
    }
}

// K=512 GEMM (8 chunks of BK=64). Chunk 0 must be staged+committed by caller.
__device__ __forceinline__ void gemm512(
    uint32_t sb, const __half* aHi, const __half* aLo, int arow0,
    const __half* bHi, const __half* bLo, int brow0,
    int tid, int w, int lane, float acc[4][4])
{
    #pragma unroll 1
    for (int kc = 0; kc < 8; ++kc) {
        const uint32_t buf = (uint32_t)kc & 1u;
        if (kc < 7) {
            const uint32_t nb = buf ^ 1u;
            stageA(sb + OFF_A + nb * A_BUF, aHi, aLo, arow0, (kc + 1) * 64, tid);
            stageB(sb + OFF_B + nb * B_BUF, bHi, bLo, brow0, (kc + 1) * 64, tid);
            CP_COMMIT();
            CP_WAIT1();
        } else {
            CP_WAIT0();
        }
        __syncthreads();
        compute_chunk<4>(sb + OFF_A + buf * A_BUF, A_PART, 144u,
                         sb + OFF_B + buf * B_BUF, B_PART, 144u, w, lane, acc);
        __syncthreads();
    }
}

__device__ __forceinline__ void grid_barrier(unsigned gen) {
    __syncthreads();
    if (threadIdx.x == 0) {
        __threadfence();
        if (atomicAdd(&g_bar_count, 1u) == (unsigned)(NCTA - 1)) {
            g_bar_count = 0u;
            __threadfence();
            g_bar_gen = gen + 1u;
        } else {
            while (g_bar_gen == gen) { }
            __threadfence();
        }
    }
    __syncthreads();
}

__global__ void __launch_bounds__(NTHR, 1) coesn_mma(
    const float* __restrict__ x,    const float* __restrict__ x2h,
    const float* __restrict__ h2h,  const float* __restrict__ h2hT,
    const float* __restrict__ bias, const float* __restrict__ gamma,
    const float* __restrict__ eps,  float* __restrict__ out, int write_final)
{
    extern __shared__ __align__(16) char smem[];
    const uint32_t sb = smem_u32(smem);
    const int tid = threadIdx.x;
    const int w = tid >> 5, lane = tid & 31;
    const int bidx = blockIdx.x;
    const int b0 = (bidx >> 4) * 128;      // 4 b-tiles
    const int h0 = (bidx & 15) * 32;       // 16 h-tiles

    unsigned gen = g_bar_gen;

    // ---- cooperative init: split weights, zero hy ----
    const int gtid = bidx * NTHR + tid;    // 0..16383
    #pragma unroll 1
    for (int e = 0; e < 16; ++e) {
        int idx = gtid + e * (NCTA * NTHR);    // 0..262143
        int r = idx >> 9, c = idx & 511;
        float v1 = h2h[(size_t)c * Hq + r];    // W1[h=r][k=c] = h2h[k][h]
        __half h1 = __float2half_rn(v1);
        g_W1_hi[idx] = h1;
        g_W1_lo[idx] = __float2half_rn(v1 - __half2float(h1));
        float v2 = -h2hT[idx];                 // W2[b][j] = -h2hT[b][j]
        __half h2v = __float2half_rn(v2);
        g_W2_hi[idx] = h2v;
        g_W2_lo[idx] = __float2half_rn(v2 - __half2float(h2v));
        __half z = __float2half_rn(0.f);
        g_hy_hi[idx] = z;
        g_hy_lo[idx] = z;
    }
    // BX = x2h^T slice [32 h][32 i], hi/lo parts (written once, read all steps)
    #pragma unroll
    for (int e = 0; e < 8; ++e) {
        int idx = tid + e * NTHR;              // 0..2047
        int part = (idx >= 1024);
        int rem = idx & 1023, r = rem >> 5, ii = rem & 31;
        float v = x2h[(size_t)ii * Hq + h0 + r];
        __half hv = __float2half_rn(v);
        __half val = part ? __float2half_rn(v - __half2float(hv)) : hv;
        *(__half*)(smem + OFF_BX + part * BX_PART + r * 80 + ii * 2) = val;
    }
    if (tid < 32) {
        ((float*)(smem + OFF_SC))[tid]      = bias[h0 + tid];
        ((float*)(smem + OFF_SC))[32 + tid] = gamma[h0 + tid];
        ((float*)(smem + OFF_SC))[64 + tid] = eps[h0 + tid];
    }
    const float* scp = (const float*)(smem + OFF_SC);
    grid_barrier(gen); gen++;

    float hyr[4][4], hzr[4][4];
    #pragma unroll
    for (int nb = 0; nb < 4; ++nb)
        #pragma unroll
        for (int j = 0; j < 4; ++j) { hyr[nb][j] = 0.f; hzr[nb][j] = 0.f; }

    #pragma unroll 1
    for (int t = 0; t < Lq; ++t) {
        // ===== Phase 1: D1 = hy @ h2h; T^T = tanh(D1 + bias)^T =====
        float acc[4][4];
        #pragma unroll
        for (int nb = 0; nb < 4; ++nb)
            #pragma unroll
            for (int j = 0; j < 4; ++j) acc[nb][j] = 0.f;

        stageA(sb + OFF_A, g_hy_hi, g_hy_lo, b0, 0, tid);
        stageB(sb + OFF_B, g_W1_hi, g_W1_lo, h0, 0, tid);
        CP_COMMIT();
        gemm512(sb, g_hy_hi, g_hy_lo, b0, g_W1_hi, g_W1_lo, h0, tid, w, lane, acc);

        // tanh + split; transpose via SMEM overlay in A-buf0 (free after gemm512)
        // layout: hi at hc*272 + bl*2 ; lo at +8704
        #pragma unroll
        for (int nb = 0; nb < 4; ++nb) {
            #pragma unroll
            for (int j = 0; j < 4; ++j) {
                int hc = nb * 8 + 2 * (lane & 3) + (j & 1);
                int bl = w * 16 + (lane >> 2) + ((j >> 1) * 8);
                float v = acc[nb][j] + scp[hc];
                float e2 = __expf(2.f * v);
                float tv = 1.f - 2.f / (e2 + 1.f);
                __half hv = __float2half_rn(tv);
                __half lv = __float2half_rn(tv - __half2float(hv));
                *(__half*)(smem + OFF_A + hc * 272 + bl * 2) = hv;
                *(__half*)(smem + OFF_A + 8704 + hc * 272 + bl * 2) = lv;
            }
        }
        __syncthreads();
        #pragma unroll
        for (int e = 0; e < 4; ++e) {          // 2 part x 32 rows x 16 uint4
            int idx = tid + e * NTHR;
            int part = (e >= 2);
            int rem = idx & 511, r = rem >> 4, q = rem & 15;
            uint4 val = *(const uint4*)(smem + OFF_A + part * 8704 + r * 272 + q * 16);
            __half* g = part ? g_Tt_lo : g_Tt_hi;
            *(uint4*)(g + (size_t)(h0 + r) * 512 + b0 + q * 8) = val;
        }
        grid_barrier(gen); gen++;

        // ===== Phase 2: D2 = x_t @ x2h - h2hT @ T =====
        stageA(sb + OFF_A, g_W2_hi, g_W2_lo, b0, 0, tid);
        stageB(sb + OFF_B, g_Tt_hi, g_Tt_lo, h0, 0, tid);
        CP_COMMIT();
        // x_t split -> X SMEM (128 rows x 32 i)
        #pragma unroll
        for (int e = 0; e < 4; ++e) {
            int idx = tid + e * NTHR;          // 0..1023 = 128 rows x 8 float4-segs
            int r = idx >> 3, q = idx & 7;
            float4 v = *(const float4*)(x + (size_t)(b0 + r) * (Lq * Iq)
                                          + (size_t)t * Iq + q * 4);
            __half h0v = __float2half_rn(v.x), h1v = __float2half_rn(v.y);
            __half h2v = __float2half_rn(v.z), h3v = __float2half_rn(v.w);
            __half l0v = __float2half_rn(v.x - __half2float(h0v));
            __half l1v = __float2half_rn(v.y - __half2float(h1v));
            __half l2v = __float2half_rn(v.z - __half2float(h2v));
            __half l3v = __float2half_rn(v.w - __half2float(h3v));
            char* dh = smem + OFF_X + r * 80 + q * 8;
            char* dl = dh + X_PART;
            *(__half2*)(dh)     = __halves2half2(h0v, h1v);
            *(__half2*)(dh + 4) = __halves2half2(h2v, h3v);
            *(__half2*)(dl)     = __halves2half2(l0v, l1v);
            *(__half2*)(dl + 4) = __halves2half2(l2v, l3v);
        }
        __syncthreads();
        #pragma unroll
        for (int nb = 0; nb < 4; ++nb)
            #pragma unroll
            for (int j = 0; j < 4; ++j) acc[nb][j] = 0.f;
        compute_chunk<2>(sb + OFF_X, X_PART, 80u,
                         sb + OFF_BX, BX_PART, 80u, w, lane, acc);
        gemm512(sb, g_W2_hi, g_W2_lo, b0, g_Tt_hi, g_Tt_lo, h0, tid, w, lane, acc);

        // integrate state in regs; hy -> SMEM float tile (row stride 144B)
        #pragma unroll
        for (int nb = 0; nb < 4; ++nb) {
            #pragma unroll
            for (int j = 0; j < 4; ++j) {
                int hc = nb * 8 + 2 * (lane & 3) + (j & 1);
                int bl = w * 16 + (lane >> 2) + ((j >> 1) * 8);
                float hy = hyr[nb][j], hz = hzr[nb][j];
                hz += DTF * (acc[nb][j] - scp[32 + hc] * hy - scp[64 + hc] * hz);
                hy += DTF * hz;
                hzr[nb][j] = hz; hyr[nb][j] = hy;
                *(float*)(smem + OFF_A + bl * 144 + hc * 4) = hy;
            }
        }
        __syncthreads();
        #pragma unroll
        for (int e = 0; e < 4; ++e) {
            int idx = tid + e * NTHR;          // 0..1023 = 128 rows x 8 float4
            int r = idx >> 3, q = idx & 7;
            float4 v = *(const float4*)(smem + OFF_A + r * 144 + q * 16);
            *(float4*)(out + (size_t)(b0 + r) * (Lq * Hq) + (size_t)t * Hq
                           + h0 + q * 4) = v;
            __half a0 = __float2half_rn(v.x), a1 = __float2half_rn(v.y);
            __half a2 = __float2half_rn(v.z), a3 = __float2half_rn(v.w);
            __half c0 = __float2half_rn(v.x - __half2float(a0));
            __half c1 = __float2half_rn(v.y - __half2float(a1));
            __half c2 = __float2half_rn(v.z - __half2float(a2));
            __half c3 = __float2half_rn(v.w - __half2float(a3));
            size_t o = (size_t)(b0 + r) * 512 + h0 + q * 4;
            *(__half2*)(g_hy_hi + o)     = __halves2half2(a0, a1);
            *(__half2*)(g_hy_hi + o + 2) = __halves2half2(a2, a3);
            *(__half2*)(g_hy_lo + o)     = __halves2half2(c0, c1);
            *(__half2*)(g_hy_lo + o + 2) = __halves2half2(c2, c3);
        }
        grid_barrier(gen); gen++;
    }

    // final hy (second output)
    if (write_final) {
        #pragma unroll
        for (int nb = 0; nb < 4; ++nb) {
            #pragma unroll
            for (int j = 0; j < 4; ++j) {
                int hc = nb * 8 + 2 * (lane & 3) + (j & 1);
                int bl = w * 16 + (lane >> 2) + ((j >> 1) * 8);
                out[(size_t)Bq * Lq * Hq + (size_t)(b0 + bl) * Hq + h0 + hc] = hyr[nb][j];
            }
        }
    }
}

extern "C" void kernel_launch(void* const* d_in, const int* in_sizes, int n_in,
                              void* d_out, int out_size) {
    const float* x    = (const float*)d_in[0];
    const float* x2h  = (const float*)d_in[1];
    const float* h2h  = (const float*)d_in[2];
    const float* h2hT = (const float*)d_in[3];
    const float* bias = (const float*)d_in[4];
    const float* gam  = (const float*)d_in[5];
    const float* eps  = (const float*)d_in[6];
    (void)in_sizes; (void)n_in;

    cudaFuncSetAttribute(coesn_mma, cudaFuncAttributeMaxDynamicSharedMemorySize, SMEM_TOT);
    const int write_final = (out_size >= Bq * Lq * Hq + Bq * Hq) ? 1 : 0;
    coesn_mma<<<NCTA, NTHR, SMEM_TOT>>>(x, x2h, h2h, h2hT, bias, gam, eps,
                                        (float*)d_out, write_final);
}

// round 6
// speedup vs baseline: 2.6742x; 1.4538x over previous
#include <cuda_runtime.h>
#include <cuda_fp16.h>
#include <cstdint>

#define Bq 512
#define Hq 512
#define Lq 512
#define Iq 32
#define DTF 0.042f
#define NCTA 128
#define NTHR 256

// ---- SMEM byte offsets ----
// A bufs:  3 x (2 part x 64 rows x 144B) = 55296
// B bufs:  3 x (2 part x 32 rows x 144B) = 27648
// W1 persistent: 2 part x 32 rows x 1040B = 66560
// X:  2 part x (64 x 80B) = 10240
// BX: 2 part x (32 x 80B) = 5120
// T:  2 part x (32 x 144B) = 9216
// O:  64 x 144B = 9216
// SC: 3 x 32 floats = 384
#define OFF_A   0
#define OFF_B   55296
#define OFF_W1  82944
#define OFF_X   149504
#define OFF_BX  159744
#define OFF_T   164864
#define OFF_O   174080
#define OFF_SC  183296
#define SMEM_TOT 183680

#define A_PART  9216u
#define A_BUF   18432u
#define B_PART  4608u
#define B_BUF   9216u
#define W1_STR  1040u
#define W1_PART 33280u
#define X_PART  5120u
#define BX_PART 2560u
#define T_PART  4608u

// ---- persistent device state ----
__device__ __align__(256) __half g_hy_hi[Bq*Hq], g_hy_lo[Bq*Hq];
__device__ __align__(256) __half g_Tt_hi[Hq*Bq], g_Tt_lo[Hq*Bq];   // T^T: [h][b]
__device__ __align__(256) __half g_W1_hi[Hq*Hq], g_W1_lo[Hq*Hq];   // h2h^T: [h][k]
__device__ __align__(256) __half g_W2_hi[Hq*Hq], g_W2_lo[Hq*Hq];   // -h2hT: [b][j]
__device__ unsigned g_bar_count = 0u;
__device__ volatile unsigned g_bar_gen = 0u;

__device__ __forceinline__ uint32_t smem_u32(const void* p) {
    uint32_t a;
    asm("{ .reg .u64 t; cvta.to.shared.u64 t, %1; cvt.u32.u64 %0, t; }" : "=r"(a) : "l"(p));
    return a;
}
#define CP_ASYNC16(dst, src) \
    asm volatile("cp.async.cg.shared.global [%0], [%1], 16;" :: "r"(dst), "l"(src) : "memory")
#define CP_COMMIT() asm volatile("cp.async.commit_group;" ::: "memory")
#define CP_WAIT0()  asm volatile("cp.async.wait_group 0;" ::: "memory")
#define CP_WAIT1()  asm volatile("cp.async.wait_group 1;" ::: "memory")
#define LDSM4(r0,r1,r2,r3, addr) \
    asm volatile("ldmatrix.sync.aligned.m8n8.x4.shared.b16 {%0,%1,%2,%3}, [%4];" \
        : "=r"(r0), "=r"(r1), "=r"(r2), "=r"(r3) : "r"(addr))

__device__ __forceinline__ void mma16816(float* c, uint32_t a0, uint32_t a1, uint32_t a2,
                                         uint32_t a3, uint32_t b0, uint32_t b1) {
    asm volatile(
        "mma.sync.aligned.m16n8k16.row.col.f32.f16.f16.f32 "
        "{%0,%1,%2,%3}, {%4,%5,%6,%7}, {%8,%9}, {%0,%1,%2,%3};"
        : "+f"(c[0]), "+f"(c[1]), "+f"(c[2]), "+f"(c[3])
        : "r"(a0), "r"(a1), "r"(a2), "r"(a3), "r"(b0), "r"(b1));
}

// ---- staging: padded SMEM rows of 144B (64 k-halves = 128B data) ----
__device__ __forceinline__ void stageA64(uint32_t dst0, const __half* __restrict__ ghi,
                                         const __half* __restrict__ glo,
                                         int row0, int k0, int tid) {
    #pragma unroll
    for (int e = 0; e < 4; ++e) {                 // 2 part x 64 rows x 8 segs
        int idx = tid + e * NTHR;
        const __half* g = (e < 2) ? ghi : glo;
        uint32_t po = (e < 2) ? 0u : A_PART;
        int rem = idx & 511, r = rem >> 3, seg = rem & 7;
        CP_ASYNC16(dst0 + po + (uint32_t)(r * 144 + seg * 16),
                   g + (size_t)(row0 + r) * 512 + k0 + seg * 8);
    }
}
__device__ __forceinline__ void stageB32(uint32_t dst0, const __half* __restrict__ ghi,
                                         const __half* __restrict__ glo,
                                         int row0, int k0, int tid) {
    #pragma unroll
    for (int e = 0; e < 2; ++e) {                 // 2 part x 32 rows x 8 segs
        int idx = tid + e * NTHR;
        const __half* g = (e < 1) ? ghi : glo;
        uint32_t po = (e < 1) ? 0u : B_PART;
        int rem = idx & 255, r = rem >> 3, seg = rem & 7;
        CP_ASYNC16(dst0 + po + (uint32_t)(r * 144 + seg * 16),
                   g + (size_t)(row0 + r) * 512 + k0 + seg * 8);
    }
}

// one BK chunk: NKS k16-steps, warp tile m16 x n16, split-fp16 (6 mma / k16)
template<int NKS>
__device__ __forceinline__ void compute_chunk(
    uint32_t aBase, uint32_t aPart, uint32_t aStr,
    uint32_t bBase, uint32_t bPart, uint32_t bStr,
    int mw, int nw, int lane, float acc[2][4])
{
    const int m = lane >> 3, rr = lane & 7;
    const uint32_t aAddr = aBase + (uint32_t)(mw * 16 + (m & 1) * 8 + rr) * aStr
                         + (uint32_t)((m >> 1) * 16);
    const uint32_t bAddr = bBase + (uint32_t)(nw * 16 + (m >> 1) * 8 + rr) * bStr
                         + (uint32_t)((m & 1) * 16);
    #pragma unroll
    for (int ks = 0; ks < NKS; ++ks) {
        uint32_t ah0, ah1, ah2, ah3, al0, al1, al2, al3;
        LDSM4(ah0, ah1, ah2, ah3, aAddr + ks * 32);
        LDSM4(al0, al1, al2, al3, aAddr + aPart + ks * 32);
        uint32_t bh0, bh1, bh2, bh3, bl0, bl1, bl2, bl3;
        LDSM4(bh0, bh1, bh2, bh3, bAddr + ks * 32);
        LDSM4(bl0, bl1, bl2, bl3, bAddr + bPart + ks * 32);
        mma16816(acc[0], ah0, ah1, ah2, ah3, bh0, bh1);
        mma16816(acc[0], ah0, ah1, ah2, ah3, bl0, bl1);
        mma16816(acc[0], al0, al1, al2, al3, bh0, bh1);
        mma16816(acc[1], ah0, ah1, ah2, ah3, bh2, bh3);
        mma16816(acc[1], ah0, ah1, ah2, ah3, bl2, bl3);
        mma16816(acc[1], al0, al1, al2, al3, bh2, bh3);
    }
}

__device__ __forceinline__ void grid_barrier(unsigned gen) {
    __syncthreads();
    if (threadIdx.x == 0) {
        __threadfence();
        if (atomicAdd(&g_bar_count, 1u) == (unsigned)(NCTA - 1)) {
            g_bar_count = 0u;
            __threadfence();
            g_bar_gen = gen + 1u;
        } else {
            while (g_bar_gen == gen) { }
            __threadfence();
        }
    }
    __syncthreads();
}

__global__ void __launch_bounds__(NTHR, 1) coesn_mma(
    const float* __restrict__ x,    const float* __restrict__ x2h,
    const float* __restrict__ h2h,  const float* __restrict__ h2hT,
    const float* __restrict__ bias, const float* __restrict__ gamma,
    const float* __restrict__ eps,  float* __restrict__ out, int write_final)
{
    extern __shared__ __align__(16) char smem[];
    const uint32_t sb = smem_u32(smem);
    const int tid = threadIdx.x;
    const int w = tid >> 5, lane = tid & 31;
    const int mw = w & 3, nw = w >> 2;         // 4 m-warps x 2 n-warps
    const int bidx = blockIdx.x;
    const int b0 = (bidx >> 4) * 64;           // 8 b-tiles
    const int h0 = (bidx & 15) * 32;           // 16 h-tiles

    unsigned gen = g_bar_gen;

    // ---- cooperative init: split weights, zero hy ----
    const int gtid = bidx * NTHR + tid;        // 0..32767
    #pragma unroll 1
    for (int e = 0; e < 8; ++e) {
        int idx = gtid + e * (NCTA * NTHR);    // 0..262143
        int r = idx >> 9, c = idx & 511;
        float v1 = h2h[(size_t)c * Hq + r];    // W1[h=r][k=c] = h2h[k][h]
        __half h1 = __float2half_rn(v1);
        g_W1_hi[idx] = h1;
        g_W1_lo[idx] = __float2half_rn(v1 - __half2float(h1));
        float v2 = -h2hT[idx];                 // W2[b][j] = -h2hT[b][j]
        __half h2v = __float2half_rn(v2);
        g_W2_hi[idx] = h2v;
        g_W2_lo[idx] = __float2half_rn(v2 - __half2float(h2v));
        __half z = __float2half_rn(0.f);
        g_hy_hi[idx] = z;
        g_hy_lo[idx] = z;
    }
    // BX = x2h^T slice [32 h][32 i]
    #pragma unroll
    for (int e = 0; e < 8; ++e) {
        int idx = tid + e * NTHR;              // 0..2047
        int part = (idx >= 1024);
        int rem = idx & 1023, r = rem >> 5, ii = rem & 31;
        float v = x2h[(size_t)ii * Hq + h0 + r];
        __half hv = __float2half_rn(v);
        __half val = part ? __float2half_rn(v - __half2float(hv)) : hv;
        *(__half*)(smem + OFF_BX + part * BX_PART + r * 80 + ii * 2) = val;
    }
    if (tid < 32) {
        ((float*)(smem + OFF_SC))[tid]      = bias[h0 + tid];
        ((float*)(smem + OFF_SC))[32 + tid] = gamma[h0 + tid];
        ((float*)(smem + OFF_SC))[64 + tid] = eps[h0 + tid];
    }
    const float* scp = (const float*)(smem + OFF_SC);
    grid_barrier(gen); gen++;                  // weight splits visible chip-wide

    // W1 slice -> persistent SMEM (2 part x 32 rows x 512 halves, stride 1040B)
    #pragma unroll
    for (int e = 0; e < 16; ++e) {
        int idx = tid + e * NTHR;              // 0..4095
        int part = (idx >= 2048);
        int rem = idx & 2047, r = rem >> 6, seg = rem & 63;
        const __half* g = part ? g_W1_lo : g_W1_hi;
        CP_ASYNC16(sb + OFF_W1 + (uint32_t)part * W1_PART + (uint32_t)(r * 1040 + seg * 16),
                   g + (size_t)(h0 + r) * 512 + seg * 8);
    }
    CP_COMMIT(); CP_WAIT0();
    __syncthreads();

    float hyr[2][4], hzr[2][4];
    #pragma unroll
    for (int p = 0; p < 2; ++p)
        #pragma unroll
        for (int j = 0; j < 4; ++j) { hyr[p][j] = 0.f; hzr[p][j] = 0.f; }

    #pragma unroll 1
    for (int t = 0; t < Lq; ++t) {
        // ===== Phase 1: D1 = hy @ h2h; T^T = tanh(D1 + bias)^T =====
        float acc[2][4];
        #pragma unroll
        for (int p = 0; p < 2; ++p)
            #pragma unroll
            for (int j = 0; j < 4; ++j) acc[p][j] = 0.f;

        stageA64(sb + OFF_A,          g_hy_hi, g_hy_lo, b0, 0,  tid); CP_COMMIT();
        stageA64(sb + OFF_A + A_BUF,  g_hy_hi, g_hy_lo, b0, 64, tid); CP_COMMIT();
        #pragma unroll 1
        for (int kc = 0; kc < 8; ++kc) {
            if (kc < 7) { CP_WAIT1(); } else { CP_WAIT0(); }
            __syncthreads();
            if (kc + 2 < 8) {
                stageA64(sb + OFF_A + (uint32_t)((kc + 2) % 3) * A_BUF,
                         g_hy_hi, g_hy_lo, b0, (kc + 2) * 64, tid);
                CP_COMMIT();
            }
            compute_chunk<4>(sb + OFF_A + (uint32_t)(kc % 3) * A_BUF, A_PART, 144u,
                             sb + OFF_W1 + (uint32_t)(kc * 128), W1_PART, W1_STR,
                             mw, nw, lane, acc);
        }

        // tanh + split -> T smem (dedicated region, own slots)
        #pragma unroll
        for (int p = 0; p < 2; ++p) {
            #pragma unroll
            for (int j = 0; j < 4; ++j) {
                int hc = nw * 16 + p * 8 + 2 * (lane & 3) + (j & 1);
                int bl = mw * 16 + (lane >> 2) + ((j >> 1) * 8);
                float v = acc[p][j] + scp[hc];
                float e2 = __expf(2.f * v);
                float tv = 1.f - 2.f / (e2 + 1.f);
                __half hv = __float2half_rn(tv);
                __half lv = __float2half_rn(tv - __half2float(hv));
                *(__half*)(smem + OFF_T + hc * 144 + bl * 2) = hv;
                *(__half*)(smem + OFF_T + T_PART + hc * 144 + bl * 2) = lv;
            }
        }
        __syncthreads();
        #pragma unroll
        for (int e = 0; e < 2; ++e) {          // 2 part x 32 rows x 8 uint4
            int idx = tid + e * NTHR;
            int part = idx >> 8;
            int rem = idx & 255, r = rem >> 3, q = rem & 7;
            uint4 val = *(const uint4*)(smem + OFF_T + part * T_PART + r * 144 + q * 16);
            __half* g = part ? g_Tt_lo : g_Tt_hi;
            *(uint4*)(g + (size_t)(h0 + r) * 512 + b0 + q * 8) = val;
        }
        grid_barrier(gen); gen++;

        // ===== Phase 2: D2 = x_t @ x2h - h2hT @ T =====
        stageA64(sb + OFF_A,         g_W2_hi, g_W2_lo, b0, 0, tid);
        stageB32(sb + OFF_B,         g_Tt_hi, g_Tt_lo, h0, 0, tid);
        CP_COMMIT();
        stageA64(sb + OFF_A + A_BUF, g_W2_hi, g_W2_lo, b0, 64, tid);
        stageB32(sb + OFF_B + B_BUF, g_Tt_hi, g_Tt_lo, h0, 64, tid);
        CP_COMMIT();
        // x_t split -> X SMEM (64 rows x 32 i)
        #pragma unroll
        for (int e = 0; e < 2; ++e) {
            int idx = tid + e * NTHR;          // 0..511 = 64 rows x 8 float4-segs
            int r = idx >> 3, q = idx & 7;
            float4 v = *(const float4*)(x + (size_t)(b0 + r) * (Lq * Iq)
                                          + (size_t)t * Iq + q * 4);
            __half h0v = __float2half_rn(v.x), h1v = __float2half_rn(v.y);
            __half h2v = __float2half_rn(v.z), h3v = __float2half_rn(v.w);
            __half l0v = __float2half_rn(v.x - __half2float(h0v));
            __half l1v = __float2half_rn(v.y - __half2float(h1v));
            __half l2v = __float2half_rn(v.z - __half2float(h2v));
            __half l3v = __float2half_rn(v.w - __half2float(h3v));
            char* dh = smem + OFF_X + r * 80 + q * 8;
            char* dl = dh + X_PART;
            *(__half2*)(dh)     = __halves2half2(h0v, h1v);
            *(__half2*)(dh + 4) = __halves2half2(h2v, h3v);
            *(__half2*)(dl)     = __halves2half2(l0v, l1v);
            *(__half2*)(dl + 4) = __halves2half2(l2v, l3v);
        }
        __syncthreads();
        #pragma unroll
        for (int p = 0; p < 2; ++p)
            #pragma unroll
            for (int j = 0; j < 4; ++j) acc[p][j] = 0.f;
        compute_chunk<2>(sb + OFF_X, X_PART, 80u,
                         sb + OFF_BX, BX_PART, 80u, mw, nw, lane, acc);
        #pragma unroll 1
        for (int kc = 0; kc < 8; ++kc) {
            if (kc < 7) { CP_WAIT1(); } else { CP_WAIT0(); }
            __syncthreads();
            if (kc + 2 < 8) {
                stageA64(sb + OFF_A + (uint32_t)((kc + 2) % 3) * A_BUF,
                         g_W2_hi, g_W2_lo, b0, (kc + 2) * 64, tid);
                stageB32(sb + OFF_B + (uint32_t)((kc + 2) % 3) * B_BUF,
                         g_Tt_hi, g_Tt_lo, h0, (kc + 2) * 64, tid);
                CP_COMMIT();
            }
            compute_chunk<4>(sb + OFF_A + (uint32_t)(kc % 3) * A_BUF, A_PART, 144u,
                             sb + OFF_B + (uint32_t)(kc % 3) * B_BUF, B_PART, 144u,
                             mw, nw, lane, acc);
        }

        // integrate state in regs; hy -> O smem tile (stride 144B)
        #pragma unroll
        for (int p = 0; p < 2; ++p) {
            #pragma unroll
            for (int j = 0; j < 4; ++j) {
                int hc = nw * 16 + p * 8 + 2 * (lane & 3) + (j & 1);
                int bl = mw * 16 + (lane >> 2) + ((j >> 1) * 8);
                float hy = hyr[p][j], hz = hzr[p][j];
                hz += DTF * (acc[p][j] - scp[32 + hc] * hy - scp[64 + hc] * hz);
                hy += DTF * hz;
                hzr[p][j] = hz; hyr[p][j] = hy;
                *(float*)(smem + OFF_O + bl * 144 + hc * 4) = hy;
            }
        }
        __syncthreads();
        #pragma unroll
        for (int e = 0; e < 2; ++e) {
            int idx = tid + e * NTHR;          // 0..511 = 64 rows x 8 float4
            int r = idx >> 3, q = idx & 7;
            float4 v = *(const float4*)(smem + OFF_O + r * 144 + q * 16);
            *(float4*)(out + (size_t)(b0 + r) * (Lq * Hq) + (size_t)t * Hq
                           + h0 + q * 4) = v;
            __half a0 = __float2half_rn(v.x), a1 = __float2half_rn(v.y);
            __half a2 = __float2half_rn(v.z), a3 = __float2half_rn(v.w);
            __half c0 = __float2half_rn(v.x - __half2float(a0));
            __half c1 = __float2half_rn(v.y - __half2float(a1));
            __half c2 = __float2half_rn(v.z - __half2float(a2));
            __half c3 = __float2half_rn(v.w - __half2float(a3));
            size_t o = (size_t)(b0 + r) * 512 + h0 + q * 4;
            *(__half2*)(g_hy_hi + o)     = __halves2half2(a0, a1);
            *(__half2*)(g_hy_hi + o + 2) = __halves2half2(a2, a3);
            *(__half2*)(g_hy_lo + o)     = __halves2half2(c0, c1);
            *(__half2*)(g_hy_lo + o + 2) = __halves2half2(c2, c3);
        }
        grid_barrier(gen); gen++;
    }

    // final hy (second output)
    if (write_final) {
        #pragma unroll
        for (int p = 0; p < 2; ++p) {
            #pragma unroll
            for (int j = 0; j < 4; ++j) {
                int hc = nw * 16 + p * 8 + 2 * (lane & 3) + (j & 1);
                int bl = mw * 16 + (lane >> 2) + ((j >> 1) * 8);
                out[(size_t)Bq * Lq * Hq + (size_t)(b0 + bl) * Hq + h0 + hc] = hyr[p][j];
            }
        }
    }
}

extern "C" void kernel_launch(void* const* d_in, const int* in_sizes, int n_in,
                              void* d_out, int out_size) {
    const float* x    = (const float*)d_in[0];
    const float* x2h  = (const float*)d_in[1];
    const float* h2h  = (const float*)d_in[2];
    const float* h2hT = (const float*)d_in[3];
    const float* bias = (const float*)d_in[4];
    const float* gam  = (const float*)d_in[5];
    const float* eps  = (const float*)d_in[6];
    (void)in_sizes; (void)n_in;

    cudaFuncSetAttribute(coesn_mma, cudaFuncAttributeMaxDynamicSharedMemorySize, SMEM_TOT);
    const int write_final = (out_size >= Bq * Lq * Hq + Bq * Hq) ? 1 : 0;
    coesn_mma<<<NCTA, NTHR, SMEM_TOT>>>(x, x2h, h2h, h2hT, bias, gam, eps,
                                        (float*)d_out, write_final);
}

// round 7
// speedup vs baseline: 2.6876x; 1.0050x over previous
#include <cuda_runtime.h>
#include <cuda_fp16.h>
#include <cstdint>

#define Bq 512
#define Hq 512
#define Lq 512
#define Iq 32
#define DTF 0.042f
#define NCTA 128
#define NTHR 256

// ---- SMEM layout (bytes) ----
// A bufs: 3 x (2 part x 64 rows x 272B) = 104448
// B bufs: 3 x (2 part x 32 rows x 272B) = 52224
// X:  2 part x (64 x 80B) = 10240
// BX: 2 part x (32 x 80B) = 5120
// T:  2 part x (32 x 144B) = 9216
// O:  64 x 144B = 9216
// SC: 3 x 32 floats = 384
#define OFF_A   0
#define OFF_B   104448
#define OFF_X   156672
#define OFF_BX  166912
#define OFF_T   172032
#define OFF_O   181248
#define OFF_SC  190464
#define SMEM_TOT 190848

#define A_PART  17408u
#define A_BUF   34816u
#define B_PART  8704u
#define B_BUF   17408u
#define X_PART  5120u
#define BX_PART 2560u
#define T_PART  4608u

// ---- persistent device state ----
__device__ __align__(256) __half g_hy_hi[Bq*Hq], g_hy_lo[Bq*Hq];
__device__ __align__(256) __half g_Tt_hi[Hq*Bq], g_Tt_lo[Hq*Bq];   // T^T: [h][b]
__device__ __align__(256) __half g_W1_hi[Hq*Hq], g_W1_lo[Hq*Hq];   // h2h^T: [h][k]
__device__ __align__(256) __half g_W2_hi[Hq*Hq], g_W2_lo[Hq*Hq];   // -h2hT: [b][j]
__device__ unsigned g_bar_count = 0u;
__device__ volatile unsigned g_bar_gen = 0u;

__device__ __forceinline__ uint32_t smem_u32(const void* p) {
    uint32_t a;
    asm("{ .reg .u64 t; cvta.to.shared.u64 t, %1; cvt.u32.u64 %0, t; }" : "=r"(a) : "l"(p));
    return a;
}
#define CP_ASYNC16(dst, src) \
    asm volatile("cp.async.cg.shared.global [%0], [%1], 16;" :: "r"(dst), "l"(src) : "memory")
#define CP_COMMIT() asm volatile("cp.async.commit_group;" ::: "memory")
#define CP_WAIT0()  asm volatile("cp.async.wait_group 0;" ::: "memory")
#define CP_WAIT1()  asm volatile("cp.async.wait_group 1;" ::: "memory")
#define LDSM4(r0,r1,r2,r3, addr) \
    asm volatile("ldmatrix.sync.aligned.m8n8.x4.shared.b16 {%0,%1,%2,%3}, [%4];" \
        : "=r"(r0), "=r"(r1), "=r"(r2), "=r"(r3) : "r"(addr))

__device__ __forceinline__ void mma16816(float* c, uint32_t a0, uint32_t a1, uint32_t a2,
                                         uint32_t a3, uint32_t b0, uint32_t b1) {
    asm volatile(
        "mma.sync.aligned.m16n8k16.row.col.f32.f16.f16.f32 "
        "{%0,%1,%2,%3}, {%4,%5,%6,%7}, {%8,%9}, {%0,%1,%2,%3};"
        : "+f"(c[0]), "+f"(c[1]), "+f"(c[2]), "+f"(c[3])
        : "r"(a0), "r"(a1), "r"(a2), "r"(a3), "r"(b0), "r"(b1));
}

// ---- staging: BK=128, padded SMEM rows of 272B (128 halves = 256B data) ----
__device__ __forceinline__ void stageA128(uint32_t dst0, const __half* __restrict__ ghi,
                                          const __half* __restrict__ glo,
                                          int row0, int k0, int tid) {
    #pragma unroll
    for (int e = 0; e < 8; ++e) {                 // 2 part x 64 rows x 16 segs
        int idx = tid + e * NTHR;
        const __half* g = (e < 4) ? ghi : glo;
        uint32_t po = (e < 4) ? 0u : A_PART;
        int rem = idx & 1023, r = rem >> 4, seg = rem & 15;
        CP_ASYNC16(dst0 + po + (uint32_t)(r * 272 + seg * 16),
                   g + (size_t)(row0 + r) * 512 + k0 + seg * 8);
    }
}
__device__ __forceinline__ void stageB128(uint32_t dst0, const __half* __restrict__ ghi,
                                          const __half* __restrict__ glo,
                                          int row0, int k0, int tid) {
    #pragma unroll
    for (int e = 0; e < 4; ++e) {                 // 2 part x 32 rows x 16 segs
        int idx = tid + e * NTHR;
        const __half* g = (e < 2) ? ghi : glo;
        uint32_t po = (e < 2) ? 0u : B_PART;
        int rem = idx & 511, r = rem >> 4, seg = rem & 15;
        CP_ASYNC16(dst0 + po + (uint32_t)(r * 272 + seg * 16),
                   g + (size_t)(row0 + r) * 512 + k0 + seg * 8);
    }
}

// one chunk: NKS k16-steps, warp tile m16 x n16, split-fp16 (6 mma / k16)
template<int NKS>
__device__ __forceinline__ void compute_chunk(
    uint32_t aBase, uint32_t aPart, uint32_t aStr,
    uint32_t bBase, uint32_t bPart, uint32_t bStr,
    int mw, int nw, int lane, float acc[2][4])
{
    const int m = lane >> 3, rr = lane & 7;
    const uint32_t aAddr = aBase + (uint32_t)(mw * 16 + (m & 1) * 8 + rr) * aStr
                         + (uint32_t)((m >> 1) * 16);
    const uint32_t bAddr = bBase + (uint32_t)(nw * 16 + (m >> 1) * 8 + rr) * bStr
                         + (uint32_t)((m & 1) * 16);
    #pragma unroll
    for (int ks = 0; ks < NKS; ++ks) {
        uint32_t ah0, ah1, ah2, ah3, al0, al1, al2, al3;
        LDSM4(ah0, ah1, ah2, ah3, aAddr + ks * 32);
        LDSM4(al0, al1, al2, al3, aAddr + aPart + ks * 32);
        uint32_t bh0, bh1, bh2, bh3, bl0, bl1, bl2, bl3;
        LDSM4(bh0, bh1, bh2, bh3, bAddr + ks * 32);
        LDSM4(bl0, bl1, bl2, bl3, bAddr + bPart + ks * 32);
        mma16816(acc[0], ah0, ah1, ah2, ah3, bh0, bh1);
        mma16816(acc[0], ah0, ah1, ah2, ah3, bl0, bl1);
        mma16816(acc[0], al0, al1, al2, al3, bh0, bh1);
        mma16816(acc[1], ah0, ah1, ah2, ah3, bh2, bh3);
        mma16816(acc[1], ah0, ah1, ah2, ah3, bl2, bl3);
        mma16816(acc[1], al0, al1, al2, al3, bh2, bh3);
    }
}

__device__ __forceinline__ void grid_barrier(unsigned gen) {
    __syncthreads();
    if (threadIdx.x == 0) {
        __threadfence();
        if (atomicAdd(&g_bar_count, 1u) == (unsigned)(NCTA - 1)) {
            g_bar_count = 0u;
            __threadfence();
            g_bar_gen = gen + 1u;
        } else {
            while (g_bar_gen == gen) { }
            __threadfence();
        }
    }
    __syncthreads();
}

__global__ void __launch_bounds__(NTHR, 1) coesn_mma(
    const float* __restrict__ x,    const float* __restrict__ x2h,
    const float* __restrict__ h2h,  const float* __restrict__ h2hT,
    const float* __restrict__ bias, const float* __restrict__ gamma,
    const float* __restrict__ eps,  float* __restrict__ out, int write_final)
{
    extern __shared__ __align__(16) char smem[];
    const uint32_t sb = smem_u32(smem);
    const int tid = threadIdx.x;
    const int w = tid >> 5, lane = tid & 31;
    const int mw = w & 3, nw = w >> 2;         // 4 m-warps x 2 n-warps
    const int bidx = blockIdx.x;
    const int b0 = (bidx >> 4) * 64;           // 8 b-tiles
    const int h0 = (bidx & 15) * 32;           // 16 h-tiles

    unsigned gen = g_bar_gen;

    // ---- cooperative init: split weights, zero hy ----
    const int gtid = bidx * NTHR + tid;        // 0..32767
    #pragma unroll 1
    for (int e = 0; e < 8; ++e) {
        int idx = gtid + e * (NCTA * NTHR);    // 0..262143
        int r = idx >> 9, c = idx & 511;
        float v1 = h2h[(size_t)c * Hq + r];    // W1[h=r][k=c] = h2h[k][h]
        __half h1 = __float2half_rn(v1);
        g_W1_hi[idx] = h1;
        g_W1_lo[idx] = __float2half_rn(v1 - __half2float(h1));
        float v2 = -h2hT[idx];                 // W2[b][j] = -h2hT[b][j]
        __half h2v = __float2half_rn(v2);
        g_W2_hi[idx] = h2v;
        g_W2_lo[idx] = __float2half_rn(v2 - __half2float(h2v));
        __half z = __float2half_rn(0.f);
        g_hy_hi[idx] = z;
        g_hy_lo[idx] = z;
    }
    // BX = x2h^T slice [32 h][32 i]
    #pragma unroll
    for (int e = 0; e < 8; ++e) {
        int idx = tid + e * NTHR;              // 0..2047
        int part = (idx >= 1024);
        int rem = idx & 1023, r = rem >> 5, ii = rem & 31;
        float v = x2h[(size_t)ii * Hq + h0 + r];
        __half hv = __float2half_rn(v);
        __half val = part ? __float2half_rn(v - __half2float(hv)) : hv;
        *(__half*)(smem + OFF_BX + part * BX_PART + r * 80 + ii * 2) = val;
    }
    if (tid < 32) {
        ((float*)(smem + OFF_SC))[tid]      = bias[h0 + tid];
        ((float*)(smem + OFF_SC))[32 + tid] = gamma[h0 + tid];
        ((float*)(smem + OFF_SC))[64 + tid] = eps[h0 + tid];
    }
    const float* scp = (const float*)(smem + OFF_SC);
    grid_barrier(gen); gen++;                  // weight splits visible chip-wide

    float hyr[2][4], hzr[2][4];
    #pragma unroll
    for (int p = 0; p < 2; ++p)
        #pragma unroll
        for (int j = 0; j < 4; ++j) { hyr[p][j] = 0.f; hzr[p][j] = 0.f; }

    #pragma unroll 1
    for (int t = 0; t < Lq; ++t) {
        // ===== Phase 1: D1 = hy @ h2h; T^T = tanh(D1 + bias)^T =====
        float acc[2][4];
        #pragma unroll
        for (int p = 0; p < 2; ++p)
            #pragma unroll
            for (int j = 0; j < 4; ++j) acc[p][j] = 0.f;

        stageA128(sb + OFF_A,         g_hy_hi, g_hy_lo, b0, 0,   tid);
        stageB128(sb + OFF_B,         g_W1_hi, g_W1_lo, h0, 0,   tid);
        CP_COMMIT();
        stageA128(sb + OFF_A + A_BUF, g_hy_hi, g_hy_lo, b0, 128, tid);
        stageB128(sb + OFF_B + B_BUF, g_W1_hi, g_W1_lo, h0, 128, tid);
        CP_COMMIT();
        #pragma unroll 1
        for (int kc = 0; kc < 4; ++kc) {
            if (kc < 3) { CP_WAIT1(); } else { CP_WAIT0(); }
            __syncthreads();
            if (kc + 2 < 4) {
                stageA128(sb + OFF_A + (uint32_t)((kc + 2) % 3) * A_BUF,
                          g_hy_hi, g_hy_lo, b0, (kc + 2) * 128, tid);
                stageB128(sb + OFF_B + (uint32_t)((kc + 2) % 3) * B_BUF,
                          g_W1_hi, g_W1_lo, h0, (kc + 2) * 128, tid);
                CP_COMMIT();
            }
            compute_chunk<8>(sb + OFF_A + (uint32_t)(kc % 3) * A_BUF, A_PART, 272u,
                             sb + OFF_B + (uint32_t)(kc % 3) * B_BUF, B_PART, 272u,
                             mw, nw, lane, acc);
        }

        // tanh + split -> T smem
        #pragma unroll
        for (int p = 0; p < 2; ++p) {
            #pragma unroll
            for (int j = 0; j < 4; ++j) {
                int hc = nw * 16 + p * 8 + 2 * (lane & 3) + (j & 1);
                int bl = mw * 16 + (lane >> 2) + ((j >> 1) * 8);
                float v = acc[p][j] + scp[hc];
                float e2 = __expf(2.f * v);
                float tv = 1.f - 2.f / (e2 + 1.f);
                __half hv = __float2half_rn(tv);
                __half lv = __float2half_rn(tv - __half2float(hv));
                *(__half*)(smem + OFF_T + hc * 144 + bl * 2) = hv;
                *(__half*)(smem + OFF_T + T_PART + hc * 144 + bl * 2) = lv;
            }
        }
        __syncthreads();
        #pragma unroll
        for (int e = 0; e < 2; ++e) {          // 2 part x 32 rows x 8 uint4
            int idx = tid + e * NTHR;
            int part = idx >> 8;
            int rem = idx & 255, r = rem >> 3, q = rem & 7;
            uint4 val = *(const uint4*)(smem + OFF_T + part * T_PART + r * 144 + q * 16);
            __half* g = part ? g_Tt_lo : g_Tt_hi;
            *(uint4*)(g + (size_t)(h0 + r) * 512 + b0 + q * 8) = val;
        }
        grid_barrier(gen); gen++;

        // ===== Phase 2: D2 = x_t @ x2h - h2hT @ T =====
        stageA128(sb + OFF_A,         g_W2_hi, g_W2_lo, b0, 0,   tid);
        stageB128(sb + OFF_B,         g_Tt_hi, g_Tt_lo, h0, 0,   tid);
        CP_COMMIT();
        stageA128(sb + OFF_A + A_BUF, g_W2_hi, g_W2_lo, b0, 128, tid);
        stageB128(sb + OFF_B + B_BUF, g_Tt_hi, g_Tt_lo, h0, 128, tid);
        CP_COMMIT();
        // x_t split -> X SMEM (visibility covered by kc=0 __syncthreads)
        #pragma unroll
        for (int e = 0; e < 2; ++e) {
            int idx = tid + e * NTHR;          // 0..511 = 64 rows x 8 float4-segs
            int r = idx >> 3, q = idx & 7;
            float4 v = *(const float4*)(x + (size_t)(b0 + r) * (Lq * Iq)
                                          + (size_t)t * Iq + q * 4);
            __half h0v = __float2half_rn(v.x), h1v = __float2half_rn(v.y);
            __half h2v = __float2half_rn(v.z), h3v = __float2half_rn(v.w);
            __half l0v = __float2half_rn(v.x - __half2float(h0v));
            __half l1v = __float2half_rn(v.y - __half2float(h1v));
            __half l2v = __float2half_rn(v.z - __half2float(h2v));
            __half l3v = __float2half_rn(v.w - __half2float(h3v));
            char* dh = smem + OFF_X + r * 80 + q * 8;
            char* dl = dh + X_PART;
            *(__half2*)(dh)     = __halves2half2(h0v, h1v);
            *(__half2*)(dh + 4) = __halves2half2(h2v, h3v);
            *(__half2*)(dl)     = __halves2half2(l0v, l1v);
            *(__half2*)(dl + 4) = __halves2half2(l2v, l3v);
        }
        #pragma unroll
        for (int p = 0; p < 2; ++p)
            #pragma unroll
            for (int j = 0; j < 4; ++j) acc[p][j] = 0.f;
        #pragma unroll 1
        for (int kc = 0; kc < 4; ++kc) {
            if (kc < 3) { CP_WAIT1(); } else { CP_WAIT0(); }
            __syncthreads();
            if (kc + 2 < 4) {
                stageA128(sb + OFF_A + (uint32_t)((kc + 2) % 3) * A_BUF,
                          g_W2_hi, g_W2_lo, b0, (kc + 2) * 128, tid);
                stageB128(sb + OFF_B + (uint32_t)((kc + 2) % 3) * B_BUF,
                          g_Tt_hi, g_Tt_lo, h0, (kc + 2) * 128, tid);
                CP_COMMIT();
            }
            if (kc == 0) {
                compute_chunk<2>(sb + OFF_X, X_PART, 80u,
                                 sb + OFF_BX, BX_PART, 80u, mw, nw, lane, acc);
            }
            compute_chunk<8>(sb + OFF_A + (uint32_t)(kc % 3) * A_BUF, A_PART, 272u,
                             sb + OFF_B + (uint32_t)(kc % 3) * B_BUF, B_PART, 272u,
                             mw, nw, lane, acc);
        }

        // integrate state in regs; hy -> O smem tile (stride 144B)
        #pragma unroll
        for (int p = 0; p < 2; ++p) {
            #pragma unroll
            for (int j = 0; j < 4; ++j) {
                int hc = nw * 16 + p * 8 + 2 * (lane & 3) + (j & 1);
                int bl = mw * 16 + (lane >> 2) + ((j >> 1) * 8);
                float hy = hyr[p][j], hz = hzr[p][j];
                hz += DTF * (acc[p][j] - scp[32 + hc] * hy - scp[64 + hc] * hz);
                hy += DTF * hz;
                hzr[p][j] = hz; hyr[p][j] = hy;
                *(float*)(smem + OFF_O + bl * 144 + hc * 4) = hy;
            }
        }
        __syncthreads();
        #pragma unroll
        for (int e = 0; e < 2; ++e) {
            int idx = tid + e * NTHR;          // 0..511 = 64 rows x 8 float4
            int r = idx >> 3, q = idx & 7;
            float4 v = *(const float4*)(smem + OFF_O + r * 144 + q * 16);
            *(float4*)(out + (size_t)(b0 + r) * (Lq * Hq) + (size_t)t * Hq
                           + h0 + q * 4) = v;
            __half a0 = __float2half_rn(v.x), a1 = __float2half_rn(v.y);
            __half a2 = __float2half_rn(v.z), a3 = __float2half_rn(v.w);
            __half c0 = __float2half_rn(v.x - __half2float(a0));
            __half c1 = __float2half_rn(v.y - __half2float(a1));
            __half c2 = __float2half_rn(v.z - __half2float(a2));
            __half c3 = __float2half_rn(v.w - __half2float(a3));
            size_t o = (size_t)(b0 + r) * 512 + h0 + q * 4;
            *(__half2*)(g_hy_hi + o)     = __halves2half2(a0, a1);
            *(__half2*)(g_hy_hi + o + 2) = __halves2half2(a2, a3);
            *(__half2*)(g_hy_lo + o)     = __halves2half2(c0, c1);
            *(__half2*)(g_hy_lo + o + 2) = __halves2half2(c2, c3);
        }
        grid_barrier(gen); gen++;
    }

    // final hy (second output)
    if (write_final) {
        #pragma unroll
        for (int p = 0; p < 2; ++p) {
            #pragma unroll
            for (int j = 0; j < 4; ++j) {
                int hc = nw * 16 + p * 8 + 2 * (lane & 3) + (j & 1);
                int bl = mw * 16 + (lane >> 2) + ((j >> 1) * 8);
                out[(size_t)Bq * Lq * Hq + (size_t)(b0 + bl) * Hq + h0 + hc] = hyr[p][j];
            }
        }
    }
}

extern "C" void kernel_launch(void* const* d_in, const int* in_sizes, int n_in,
                              void* d_out, int out_size) {
    const float* x    = (const float*)d_in[0];
    const float* x2h  = (const float*)d_in[1];
    const float* h2h  = (const float*)d_in[2];
    const float* h2hT = (const float*)d_in[3];
    const float* bias = (const float*)d_in[4];
    const float* gam  = (const float*)d_in[5];
    const float* eps  = (const float*)d_in[6];
    (void)in_sizes; (void)n_in;

    cudaFuncSetAttribute(coesn_mma, cudaFuncAttributeMaxDynamicSharedMemorySize, SMEM_TOT);
    const int write_final = (out_size >= Bq * Lq * Hq + Bq * Hq) ? 1 : 0;
    coesn_mma<<<NCTA, NTHR, SMEM_TOT>>>(x, x2h, h2h, h2hT, bias, gam, eps,
                                        (float*)d_out, write_final);
}